// round 2
// baseline (speedup 1.0000x reference)
#include <cuda_runtime.h>
#include <math.h>
#include <stdint.h>

#define NN 50000
#define EE 800000
#define DIN 384
#define DH 128

// ---------------- scratch (device globals; no allocation allowed) -------------
__device__ int   g_is64;
__device__ int   g_src[EE];
__device__ int   g_dst[EE];
__device__ float g_deg[NN];
__device__ float g_dinv[NN];
__device__ float g_hws[NN * DH];
__device__ float g_acc[NN * DH];
__device__ float g_res[NN * DH];
__device__ float g_h1 [NN * DH];

// ---------------- small helpers ----------------------------------------------
__device__ __forceinline__ unsigned long long pack2(float x, float y) {
    unsigned long long r;
    asm("mov.b64 %0, {%1, %2};" : "=l"(r) : "r"(__float_as_uint(x)), "r"(__float_as_uint(y)));
    return r;
}
__device__ __forceinline__ void fma2(unsigned long long& d, unsigned long long a, unsigned long long b) {
    asm("fma.rn.f32x2 %0, %1, %2, %0;" : "+l"(d) : "l"(a), "l"(b));
}
__device__ __forceinline__ float2 unpack2(unsigned long long v) {
    unsigned int lo, hi;
    asm("mov.b64 {%0, %1}, %2;" : "=r"(lo), "=r"(hi) : "l"(v));
    return make_float2(__uint_as_float(lo), __uint_as_float(hi));
}
__device__ __forceinline__ float elu1(float x) { return x > 0.f ? x : expm1f(x); }

// ---------------- edge dtype detect + convert ---------------------------------
__global__ void k_detect(const void* edges) {
    const unsigned long long* p = (const unsigned long long*)edges;
    int is64 = 1;
    for (int i = 0; i < 8; i++) if (p[i] >= (unsigned long long)NN) is64 = 0;
    g_is64 = is64;
}

__global__ void k_init_deg() {
    int i = blockIdx.x * blockDim.x + threadIdx.x;
    if (i < NN) g_deg[i] = 1.0f;   // self-loop
}

__global__ void k_edges(const void* edges) {
    int e = blockIdx.x * blockDim.x + threadIdx.x;
    if (e >= EE) return;
    int s, d;
    if (g_is64) {
        const long long* p = (const long long*)edges;
        s = (int)p[e]; d = (int)p[EE + e];
    } else {
        const int* p = (const int*)edges;
        s = p[e]; d = p[EE + e];
    }
    g_src[e] = s; g_dst[e] = d;
    atomicAdd(&g_deg[d], 1.0f);
}

__global__ void k_dinv() {
    int i = blockIdx.x * blockDim.x + threadIdx.x;
    if (i < NN) g_dinv[i] = rsqrtf(g_deg[i]);
}

// ---------------- SGEMM: C = A[NN x kd] * B[kd x 128] -------------------------
// mode (blockIdx.y): 0 -> write (C * dinv[row]) to g_hws and g_acc (self-loop init)
//                    1 -> write LayerNorm(C + lb; lg, lbe) to g_res
__global__ __launch_bounds__(256, 2) void k_gemm(
    const float* __restrict__ Ain,
    const float* __restrict__ B0, const float* __restrict__ B1,
    const float* __restrict__ lb, const float* __restrict__ lg, const float* __restrict__ lbe,
    int kd, int use_h1)
{
    __shared__ float As[16][128];
    __shared__ float Bs[16][128];
    const float* A = use_h1 ? (const float*)g_h1 : Ain;
    const int mode = blockIdx.y;
    const float* Bm = mode ? B1 : B0;
    const int tid = threadIdx.x;
    const int tx = tid & 15, ty = tid >> 4;
    const int row0 = blockIdx.x * 128;

    unsigned long long acc[8][4];
#pragma unroll
    for (int i = 0; i < 8; i++)
#pragma unroll
        for (int p = 0; p < 4; p++) acc[i][p] = 0ULL;

    const int ntiles = kd >> 4;
    for (int t = 0; t < ntiles; t++) {
        const int kt = t << 4;
        // load A tile 128x16 (transposed into As[k][row])
#pragma unroll
        for (int u = 0; u < 2; u++) {
            int f = tid + u * 256;
            int r = f >> 2, kq = (f & 3) << 2;
            int gr = row0 + r;
            float4 v = make_float4(0.f, 0.f, 0.f, 0.f);
            if (gr < NN) v = *(const float4*)&A[(size_t)gr * kd + kt + kq];
            As[kq + 0][r] = v.x; As[kq + 1][r] = v.y;
            As[kq + 2][r] = v.z; As[kq + 3][r] = v.w;
        }
        // load B tile 16x128
#pragma unroll
        for (int u = 0; u < 2; u++) {
            int f = tid + u * 256;
            int kr = f >> 5, c0 = (f & 31) << 2;
            *(float4*)&Bs[kr][c0] = *(const float4*)&Bm[(size_t)(kt + kr) * 128 + c0];
        }
        __syncthreads();
#pragma unroll
        for (int k = 0; k < 16; k++) {
            float4 a0 = *(const float4*)&As[k][ty * 8];
            float4 a1 = *(const float4*)&As[k][ty * 8 + 4];
            float4 b0 = *(const float4*)&Bs[k][tx * 8];
            float4 b1 = *(const float4*)&Bs[k][tx * 8 + 4];
            unsigned long long bb0 = pack2(b0.x, b0.y), bb1 = pack2(b0.z, b0.w);
            unsigned long long bb2 = pack2(b1.x, b1.y), bb3 = pack2(b1.z, b1.w);
            float av[8] = {a0.x, a0.y, a0.z, a0.w, a1.x, a1.y, a1.z, a1.w};
#pragma unroll
            for (int i = 0; i < 8; i++) {
                unsigned long long ad = pack2(av[i], av[i]);
                fma2(acc[i][0], ad, bb0);
                fma2(acc[i][1], ad, bb1);
                fma2(acc[i][2], ad, bb2);
                fma2(acc[i][3], ad, bb3);
            }
        }
        __syncthreads();
    }

    float C[8][8];
#pragma unroll
    for (int i = 0; i < 8; i++)
#pragma unroll
        for (int p = 0; p < 4; p++) {
            float2 tv = unpack2(acc[i][p]);
            C[i][2 * p] = tv.x; C[i][2 * p + 1] = tv.y;
        }
    const int c0 = tx * 8;

    if (mode == 0) {
#pragma unroll
        for (int i = 0; i < 8; i++) {
            int gr = row0 + ty * 8 + i;
            if (gr < NN) {
                float dv = g_dinv[gr];
                float4 o0 = make_float4(C[i][0] * dv, C[i][1] * dv, C[i][2] * dv, C[i][3] * dv);
                float4 o1 = make_float4(C[i][4] * dv, C[i][5] * dv, C[i][6] * dv, C[i][7] * dv);
                *(float4*)&g_hws[(size_t)gr * DH + c0]     = o0;
                *(float4*)&g_hws[(size_t)gr * DH + c0 + 4] = o1;
                *(float4*)&g_acc[(size_t)gr * DH + c0]     = o0;
                *(float4*)&g_acc[(size_t)gr * DH + c0 + 4] = o1;
            }
        }
    } else {
        float lbv[8], lgv[8], lbev[8];
#pragma unroll
        for (int j = 0; j < 8; j++) { lbv[j] = lb[c0 + j]; lgv[j] = lg[c0 + j]; lbev[j] = lbe[c0 + j]; }
#pragma unroll
        for (int i = 0; i < 8; i++) {
            float v[8]; float s = 0.f, q = 0.f;
#pragma unroll
            for (int j = 0; j < 8; j++) { v[j] = C[i][j] + lbv[j]; s += v[j]; q += v[j] * v[j]; }
#pragma unroll
            for (int o = 8; o; o >>= 1) {
                s += __shfl_xor_sync(0xffffffffu, s, o);
                q += __shfl_xor_sync(0xffffffffu, q, o);
            }
            float m = s * (1.f / DH);
            float var = q * (1.f / DH) - m * m;
            float rstd = rsqrtf(var + 1e-5f);
            int gr = row0 + ty * 8 + i;
            if (gr < NN) {
                float o_[8];
#pragma unroll
                for (int j = 0; j < 8; j++) o_[j] = (v[j] - m) * rstd * lgv[j] + lbev[j];
                *(float4*)&g_res[(size_t)gr * DH + c0]     = make_float4(o_[0], o_[1], o_[2], o_[3]);
                *(float4*)&g_res[(size_t)gr * DH + c0 + 4] = make_float4(o_[4], o_[5], o_[6], o_[7]);
            }
        }
    }
}

// ---------------- edge scatter: acc[dst] += hws[src] ---------------------------
__global__ void k_scatter() {
    int gw = (blockIdx.x * blockDim.x + threadIdx.x) >> 5;
    if (gw >= EE) return;
    int lane = threadIdx.x & 31;
    int s = g_src[gw];
    int d = g_dst[gw];
    const float4 v = *(const float4*)&g_hws[(size_t)s * DH + lane * 4];
    float* p = &g_acc[(size_t)d * DH + lane * 4];
    asm volatile("red.global.add.v4.f32 [%0], {%1,%2,%3,%4};"
                 :: "l"(p), "f"(v.x), "f"(v.y), "f"(v.z), "f"(v.w) : "memory");
}

// ---------------- epilogue 1: h1 = elu(LN(acc*dinv + b1)) + res ----------------
__global__ void k_epi1(const float* __restrict__ b1, const float* __restrict__ g1,
                       const float* __restrict__ be1) {
    int w = (blockIdx.x * blockDim.x + threadIdx.x) >> 5;
    if (w >= NN) return;
    int lane = threadIdx.x & 31;
    float dv = g_dinv[w];
    float4 a = *(const float4*)&g_acc[(size_t)w * DH + lane * 4];
    float4 bb = *(const float4*)&b1[lane * 4];
    float v0 = fmaf(a.x, dv, bb.x), v1 = fmaf(a.y, dv, bb.y);
    float v2 = fmaf(a.z, dv, bb.z), v3 = fmaf(a.w, dv, bb.w);
    float s = v0 + v1 + v2 + v3;
    float q = v0 * v0 + v1 * v1 + v2 * v2 + v3 * v3;
#pragma unroll
    for (int o = 16; o; o >>= 1) {
        s += __shfl_xor_sync(0xffffffffu, s, o);
        q += __shfl_xor_sync(0xffffffffu, q, o);
    }
    float m = s * (1.f / DH);
    float var = q * (1.f / DH) - m * m;
    float rstd = rsqrtf(var + 1e-5f);
    float4 gg = *(const float4*)&g1[lane * 4];
    float4 be = *(const float4*)&be1[lane * 4];
    float y0 = elu1((v0 - m) * rstd * gg.x + be.x);
    float y1 = elu1((v1 - m) * rstd * gg.y + be.y);
    float y2 = elu1((v2 - m) * rstd * gg.z + be.z);
    float y3 = elu1((v3 - m) * rstd * gg.w + be.w);
    float4 r = *(const float4*)&g_res[(size_t)w * DH + lane * 4];
    *(float4*)&g_h1[(size_t)w * DH + lane * 4] =
        make_float4(y0 + r.x, y1 + r.y, y2 + r.z, y3 + r.w);
}

// ---------------- epilogue 2 + MLP head + softmax ------------------------------
#define EPI2_SMEM ((128 * 128 + 8 * 4 * 132) * 4)
__global__ __launch_bounds__(256, 2) void k_epi2(
    const float* __restrict__ b2, const float* __restrict__ g2, const float* __restrict__ be2,
    const float* __restrict__ mW1, const float* __restrict__ mb1,
    const float* __restrict__ mg_, const float* __restrict__ mbe_,
    const float* __restrict__ mW2, const float* __restrict__ mb2,
    float* __restrict__ out)
{
    extern __shared__ float sm[];
    float* W1s = sm;                    // 128*128
    float* h2s = sm + 128 * 128;        // 8 warps * 4 nodes * 132
    const int tid = threadIdx.x;
    for (int i = tid; i < 128 * 128 / 4; i += 256)
        ((float4*)W1s)[i] = ((const float4*)mW1)[i];
    __syncthreads();

    const int wid = tid >> 5, lane = tid & 31;
    float* myh2 = h2s + wid * (4 * 132);
    float4 b2v  = *(const float4*)&b2 [lane * 4];
    float4 g2v  = *(const float4*)&g2 [lane * 4];
    float4 be2v = *(const float4*)&be2[lane * 4];
    float4 mb1v = *(const float4*)&mb1[lane * 4];
    float4 mgv  = *(const float4*)&mg_[lane * 4];
    float4 mbev = *(const float4*)&mbe_[lane * 4];
    float mb2v[16];
#pragma unroll
    for (int c = 0; c < 16; c++) mb2v[c] = mb2[c];

    const int gw = blockIdx.x * 8 + wid;
    const int step = gridDim.x * 8 * 4;
    for (int nb = gw * 4; nb < NN; nb += step) {
        // ---- phase A: h2 = elu(LN(acc*dinv + b2)) + h1, staged to smem ----
#pragma unroll
        for (int s2 = 0; s2 < 4; s2++) {
            int n = nb + s2;
            float4 a = make_float4(0.f, 0.f, 0.f, 0.f), r = a;
            float dv = 0.f;
            if (n < NN) {
                dv = g_dinv[n];
                a = *(const float4*)&g_acc[(size_t)n * DH + lane * 4];
                r = *(const float4*)&g_h1 [(size_t)n * DH + lane * 4];
            }
            float v0 = fmaf(a.x, dv, b2v.x), v1 = fmaf(a.y, dv, b2v.y);
            float v2 = fmaf(a.z, dv, b2v.z), v3 = fmaf(a.w, dv, b2v.w);
            float s = v0 + v1 + v2 + v3;
            float q = v0 * v0 + v1 * v1 + v2 * v2 + v3 * v3;
#pragma unroll
            for (int o = 16; o; o >>= 1) {
                s += __shfl_xor_sync(0xffffffffu, s, o);
                q += __shfl_xor_sync(0xffffffffu, q, o);
            }
            float m = s * (1.f / DH);
            float var = q * (1.f / DH) - m * m;
            float rstd = rsqrtf(var + 1e-5f);
            float y0 = elu1((v0 - m) * rstd * g2v.x + be2v.x) + r.x;
            float y1 = elu1((v1 - m) * rstd * g2v.y + be2v.y) + r.y;
            float y2 = elu1((v2 - m) * rstd * g2v.z + be2v.z) + r.z;
            float y3 = elu1((v3 - m) * rstd * g2v.w + be2v.w) + r.w;
            *(float4*)&myh2[s2 * 132 + lane * 4] = make_float4(y0, y1, y2, y3);
        }
        __syncwarp();

        // ---- phase B: z = h2 @ mW1 + mb1 (each lane: cols 4l..4l+3, 4 nodes) ----
        float4 zz[4];
#pragma unroll
        for (int s2 = 0; s2 < 4; s2++) zz[s2] = mb1v;
        for (int kk = 0; kk < 32; kk++) {
            float4 hq0 = *(const float4*)&myh2[0 * 132 + 4 * kk];
            float4 hq1 = *(const float4*)&myh2[1 * 132 + 4 * kk];
            float4 hq2 = *(const float4*)&myh2[2 * 132 + 4 * kk];
            float4 hq3 = *(const float4*)&myh2[3 * 132 + 4 * kk];
            float ha0[4] = {hq0.x, hq0.y, hq0.z, hq0.w};
            float ha1[4] = {hq1.x, hq1.y, hq1.z, hq1.w};
            float ha2[4] = {hq2.x, hq2.y, hq2.z, hq2.w};
            float ha3[4] = {hq3.x, hq3.y, hq3.z, hq3.w};
#pragma unroll
            for (int j = 0; j < 4; j++) {
                float4 w = *(const float4*)&W1s[(4 * kk + j) * 128 + lane * 4];
                zz[0].x = fmaf(ha0[j], w.x, zz[0].x); zz[0].y = fmaf(ha0[j], w.y, zz[0].y);
                zz[0].z = fmaf(ha0[j], w.z, zz[0].z); zz[0].w = fmaf(ha0[j], w.w, zz[0].w);
                zz[1].x = fmaf(ha1[j], w.x, zz[1].x); zz[1].y = fmaf(ha1[j], w.y, zz[1].y);
                zz[1].z = fmaf(ha1[j], w.z, zz[1].z); zz[1].w = fmaf(ha1[j], w.w, zz[1].w);
                zz[2].x = fmaf(ha2[j], w.x, zz[2].x); zz[2].y = fmaf(ha2[j], w.y, zz[2].y);
                zz[2].z = fmaf(ha2[j], w.z, zz[2].z); zz[2].w = fmaf(ha2[j], w.w, zz[2].w);
                zz[3].x = fmaf(ha3[j], w.x, zz[3].x); zz[3].y = fmaf(ha3[j], w.y, zz[3].y);
                zz[3].z = fmaf(ha3[j], w.z, zz[3].z); zz[3].w = fmaf(ha3[j], w.w, zz[3].w);
            }
        }
        __syncwarp();

        // ---- phase C: z = elu(LN(z; mg, mbe)) ----
#pragma unroll
        for (int s2 = 0; s2 < 4; s2++) {
            float4 z = zz[s2];
            float s = z.x + z.y + z.z + z.w;
            float q = z.x * z.x + z.y * z.y + z.z * z.z + z.w * z.w;
#pragma unroll
            for (int o = 16; o; o >>= 1) {
                s += __shfl_xor_sync(0xffffffffu, s, o);
                q += __shfl_xor_sync(0xffffffffu, q, o);
            }
            float m = s * (1.f / DH);
            float var = q * (1.f / DH) - m * m;
            float rstd = rsqrtf(var + 1e-5f);
            z.x = elu1((z.x - m) * rstd * mgv.x + mbev.x);
            z.y = elu1((z.y - m) * rstd * mgv.y + mbev.y);
            z.z = elu1((z.z - m) * rstd * mgv.z + mbev.z);
            z.w = elu1((z.w - m) * rstd * mgv.w + mbev.w);
            zz[s2] = z;
        }

        // ---- phase D: H = z @ mW2 + mb2 ; softmax ----
#pragma unroll
        for (int s2 = 0; s2 < 4; s2++) {
            float Hp[16];
#pragma unroll
            for (int c = 0; c < 16; c++) Hp[c] = 0.f;
            float za[4] = {zz[s2].x, zz[s2].y, zz[s2].z, zz[s2].w};
#pragma unroll
            for (int j = 0; j < 4; j++) {
                int k = 4 * lane + j;
                const float4* wr = (const float4*)&mW2[k * 16];
                float4 w0 = wr[0], w1 = wr[1], w2 = wr[2], w3 = wr[3];
                float zv = za[j];
                Hp[0]  = fmaf(zv, w0.x, Hp[0]);  Hp[1]  = fmaf(zv, w0.y, Hp[1]);
                Hp[2]  = fmaf(zv, w0.z, Hp[2]);  Hp[3]  = fmaf(zv, w0.w, Hp[3]);
                Hp[4]  = fmaf(zv, w1.x, Hp[4]);  Hp[5]  = fmaf(zv, w1.y, Hp[5]);
                Hp[6]  = fmaf(zv, w1.z, Hp[6]);  Hp[7]  = fmaf(zv, w1.w, Hp[7]);
                Hp[8]  = fmaf(zv, w2.x, Hp[8]);  Hp[9]  = fmaf(zv, w2.y, Hp[9]);
                Hp[10] = fmaf(zv, w2.z, Hp[10]); Hp[11] = fmaf(zv, w2.w, Hp[11]);
                Hp[12] = fmaf(zv, w3.x, Hp[12]); Hp[13] = fmaf(zv, w3.y, Hp[13]);
                Hp[14] = fmaf(zv, w3.z, Hp[14]); Hp[15] = fmaf(zv, w3.w, Hp[15]);
            }
#pragma unroll
            for (int o = 16; o; o >>= 1)
#pragma unroll
                for (int c = 0; c < 16; c++)
                    Hp[c] += __shfl_xor_sync(0xffffffffu, Hp[c], o);
            int n = nb + s2;
            if (lane == 0 && n < NN) {
                float mx = -1e30f;
#pragma unroll
                for (int c = 0; c < 16; c++) { Hp[c] += mb2v[c]; mx = fmaxf(mx, Hp[c]); }
                float ss = 0.f;
#pragma unroll
                for (int c = 0; c < 16; c++) { Hp[c] = __expf(Hp[c] - mx); ss += Hp[c]; }
                float inv = 1.f / ss;
                *(float4*)&out[(size_t)n * 16 + 0]  = make_float4(Hp[0] * inv, Hp[1] * inv, Hp[2] * inv, Hp[3] * inv);
                *(float4*)&out[(size_t)n * 16 + 4]  = make_float4(Hp[4] * inv, Hp[5] * inv, Hp[6] * inv, Hp[7] * inv);
                *(float4*)&out[(size_t)n * 16 + 8]  = make_float4(Hp[8] * inv, Hp[9] * inv, Hp[10] * inv, Hp[11] * inv);
                *(float4*)&out[(size_t)n * 16 + 12] = make_float4(Hp[12] * inv, Hp[13] * inv, Hp[14] * inv, Hp[15] * inv);
            }
        }
    }
}

// ---------------- launcher -----------------------------------------------------
extern "C" void kernel_launch(void* const* d_in, const int* in_sizes, int n_in,
                              void* d_out, int out_size) {
    const float* x   = (const float*)d_in[0];
    const void*  ei  = d_in[1];
    const float* W1  = (const float*)d_in[2];
    const float* b1  = (const float*)d_in[3];
    const float* g1  = (const float*)d_in[4];
    const float* be1 = (const float*)d_in[5];
    const float* W2  = (const float*)d_in[6];
    const float* b2  = (const float*)d_in[7];
    const float* g2  = (const float*)d_in[8];
    const float* be2 = (const float*)d_in[9];
    const float* rW  = (const float*)d_in[10];
    const float* rb  = (const float*)d_in[11];
    const float* rg  = (const float*)d_in[12];
    const float* rbe = (const float*)d_in[13];
    const float* mW1 = (const float*)d_in[14];
    const float* mb1 = (const float*)d_in[15];
    const float* mg  = (const float*)d_in[16];
    const float* mbe = (const float*)d_in[17];
    const float* mW2 = (const float*)d_in[18];
    const float* mb2 = (const float*)d_in[19];
    float* out = (float*)d_out;

    cudaFuncSetAttribute(k_epi2, cudaFuncAttributeMaxDynamicSharedMemorySize, EPI2_SMEM);

    k_detect<<<1, 1>>>(ei);
    k_init_deg<<<(NN + 255) / 256, 256>>>();
    k_edges<<<(EE + 255) / 256, 256>>>(ei);
    k_dinv<<<(NN + 255) / 256, 256>>>();

    // layer 1: x@W1 (scaled) + x@rW (LN residual)
    dim3 grid1((NN + 127) / 128, 2);
    k_gemm<<<grid1, 256>>>(x, W1, rW, rb, rg, rbe, DIN, 0);
    k_scatter<<<EE / 8, 256>>>();
    k_epi1<<<(NN * 32 + 255) / 256, 256>>>(b1, g1, be1);

    // layer 2: h1@W2 (scaled)
    dim3 grid2((NN + 127) / 128, 1);
    k_gemm<<<grid2, 256>>>(nullptr, W2, W2, rb, rg, rbe, DH, 1);
    k_scatter<<<EE / 8, 256>>>();

    // epilogue 2 + MLP head + softmax
    k_epi2<<<296, 256, EPI2_SMEM>>>(b2, g2, be2, mW1, mb1, mg, mbe, mW2, mb2, out);
}